// round 9
// baseline (speedup 1.0000x reference)
#include <cuda_runtime.h>
#include <cstdint>

#define NN 50000
#define EE 800000
#define DD 64
#define LL 3
#define RR 4

// ---------------- device scratch (static: no allocations allowed) ----------------
__device__ float g_h[NN * DD];
__device__ float g_xproj[NN * DD];
__device__ float g_p[NN * DD];
__device__ float g_tbar[NN * DD];
__device__ float g_hnew[NN * DD];
__device__ unsigned char g_keepb[LL * NN];
__device__ int g_deg[NN];
__device__ int g_rowptr[NN + 1];
__device__ int g_cursor[NN];
__device__ int g_col[EE];
__device__ int g_partials[64];
__device__ float g_bnsum[LL * DD];
__device__ float g_bnsq[LL * DD];
__device__ int g_found32;  // sticky: 0 if edge_index is int64, 1 if int32. Never reset -> idempotent.

// ---------------- helpers ----------------
__device__ __forceinline__ unsigned rotl32(unsigned v, int s) {
    return (v << s) | (v >> (32 - s));
}

// JAX threefry2x32 (20 rounds), exact
__device__ void threefry(unsigned k0, unsigned k1, unsigned x0, unsigned x1,
                         unsigned& o0, unsigned& o1) {
    unsigned ks2 = k0 ^ k1 ^ 0x1BD11BDAu;
    x0 += k0; x1 += k1;
#define TFR(r) { x0 += x1; x1 = rotl32(x1, r); x1 ^= x0; }
    TFR(13) TFR(15) TFR(26) TFR(6)   x0 += k1;  x1 += ks2 + 1u;
    TFR(17) TFR(29) TFR(16) TFR(24)  x0 += ks2; x1 += k0 + 2u;
    TFR(13) TFR(15) TFR(26) TFR(6)   x0 += k0;  x1 += k1 + 3u;
    TFR(17) TFR(29) TFR(16) TFR(24)  x0 += k1;  x1 += ks2 + 4u;
    TFR(13) TFR(15) TFR(26) TFR(6)   x0 += ks2; x1 += k0 + 5u;
#undef TFR
    o0 = x0; o1 = x1;
}

__device__ __forceinline__ float mishf(float x) {
    float sp = fmaxf(x, 0.f) + log1pf(expf(-fabsf(x)));
    return x * tanhf(sp);
}

__device__ __forceinline__ int edge_val(const void* ei, int idx) {
    if (g_found32 == 0) return (int)((const long long*)ei)[idx];
    return ((const int*)ei)[idx];
}

__device__ __forceinline__ uint32_t sm32(const void* p) {
    return (uint32_t)__cvta_generic_to_shared(p);
}

// ---------------- init + dtype detect + bn-slot zero (merged) ----------------
// If edge_index is int64, odd 32-bit words (hi halves) are all 0 (values < 50000).
// If int32, odd words are node ids (mostly nonzero). g_found32 is sticky-set, never
// cleared: same value every replay -> deterministic.
__global__ void initdetect_kernel(const unsigned* w) {
    int i = blockIdx.x * blockDim.x + threadIdx.x;
    if (i < EE && w[2 * i + 1] != 0u) g_found32 = 1;
    if (i < NN) g_deg[i] = 0;
    if (i < LL * DD) { g_bnsum[i] = 0.f; g_bnsq[i] = 0.f; }
}

// ---------------- dropout masks ----------------
// jax_threefry_partitionable=True random_bits, bit_width=32:
//   (o0, o1) = threefry(key, f >> 32, (uint32)f);  draw = o0 ^ o1
// u = bitcast(draw >> 9 | 0x3f800000) - 1;  keep = !(u < 0.2).
// fold_in: folded_key = threefry((0,42), 0, layer).
__global__ void mask_kernel() {
    int i = blockIdx.x * blockDim.x + threadIdx.x;
    if (i >= LL * NN) return;
    int lay = i / NN, n = i % NN;
    unsigned fk0, fk1;
    threefry(0u, 42u, 0u, (unsigned)lay, fk0, fk1);
    unsigned byte = 0;
#pragma unroll
    for (int r = 0; r < RR; r++) {
        unsigned o0, o1;
        threefry(fk0, fk1, 0u, (unsigned)(r * NN + n), o0, o1);
        unsigned draw = o0 ^ o1;
        float u = __uint_as_float((draw >> 9) | 0x3f800000u) - 1.0f;
        if (!(u < 0.2f)) byte |= (1u << r);
    }
    g_keepb[i] = (unsigned char)byte;
}

// ---------------- CSR build ----------------
__global__ void count_deg(const void* ei) {
    int e = blockIdx.x * blockDim.x + threadIdx.x;
    if (e < EE) atomicAdd(&g_deg[edge_val(ei, EE + e)], 1);
}

__global__ void scan1() {
    __shared__ int s[256];
    int t = threadIdx.x;
    int base = blockIdx.x * 1024 + t * 4;
    int v0 = (base + 0 < NN) ? g_deg[base + 0] : 0;
    int v1 = (base + 1 < NN) ? g_deg[base + 1] : 0;
    int v2 = (base + 2 < NN) ? g_deg[base + 2] : 0;
    int v3 = (base + 3 < NN) ? g_deg[base + 3] : 0;
    int sum = v0 + v1 + v2 + v3;
    s[t] = sum;
    __syncthreads();
#pragma unroll
    for (int off = 1; off < 256; off <<= 1) {
        int x = (t >= off) ? s[t - off] : 0;
        __syncthreads();
        s[t] += x;
        __syncthreads();
    }
    int excl = s[t] - sum;
    if (base + 0 < NN) g_rowptr[base + 0] = excl;
    if (base + 1 < NN) g_rowptr[base + 1] = excl + v0;
    if (base + 2 < NN) g_rowptr[base + 2] = excl + v0 + v1;
    if (base + 3 < NN) g_rowptr[base + 3] = excl + v0 + v1 + v2;
    if (t == 255) g_partials[blockIdx.x] = s[255];
}

__global__ void scan2() {
    __shared__ int s[64];
    int t = threadIdx.x;
    int v = (t < 49) ? g_partials[t] : 0;
    s[t] = v;
    __syncthreads();
#pragma unroll
    for (int off = 1; off < 64; off <<= 1) {
        int x = (t >= off) ? s[t - off] : 0;
        __syncthreads();
        s[t] += x;
        __syncthreads();
    }
    g_partials[t] = s[t] - v;
    if (t == 63) g_rowptr[NN] = s[63];
}

__global__ void scan3() {
    int i = blockIdx.x * blockDim.x + threadIdx.x;
    if (i < NN) {
        int v = g_rowptr[i] + g_partials[i >> 10];
        g_rowptr[i] = v;
        g_cursor[i] = v;
    }
}

__global__ void fill_csr(const void* ei) {
    int e = blockIdx.x * blockDim.x + threadIdx.x;
    if (e < EE) {
        int dst = edge_val(ei, EE + e);
        int src = edge_val(ei, e);
        int pos = atomicAdd(&g_cursor[dst], 1);
        g_col[pos] = src;
    }
}

// ---------------- GEMM (M x 64) @ (64 x 64), f32x2 packed, fused epilogues -------
// mode 0: Y = X@W
// mode 1: Y = X@W + b        (+ optional duplicate write to Y2)
// mode 2: Y = mish(X@W + b)
// mode 3: Y = X@W + b + res  + batchnorm partial sums into layer slot
// X tile is stored DUPLICATED in smem (x0,x0,x1,x1,...) so ld.shared.u64 yields the
// packed (x,x) operand for fma.rn.f32x2 with no pack instructions.
__global__ __launch_bounds__(256) void gemm64(
    const float* __restrict__ X, const float* __restrict__ W,
    const float* __restrict__ bias, const float* __restrict__ res,
    float* __restrict__ Y, float* __restrict__ Y2, int M, int mode, int layer) {
    __shared__ float XsDup[64 * 128];  // 32 KB: row r at [r*128], value k duplicated at 2k,2k+1
    __shared__ float Ws[64 * 64];      // 16 KB
    int t = threadIdx.x;
    int row0 = blockIdx.x * 64;

    const float4* W4 = (const float4*)W;
    float4* Ws4 = (float4*)Ws;
#pragma unroll
    for (int i = 0; i < 4; i++) Ws4[t + 256 * i] = W4[t + 256 * i];

    const float4* X4 = (const float4*)X;
#pragma unroll
    for (int i = 0; i < 4; i++) {
        int idx = t + 256 * i;
        int lr = idx >> 4;          // local row 0..63
        int c0 = idx & 15;          // float4 index within row
        int r = row0 + lr;
        float4 xv = (r < M) ? X4[r * 16 + c0] : make_float4(0.f, 0.f, 0.f, 0.f);
        float4* row = (float4*)(XsDup + lr * 128);
        row[c0 * 2 + 0] = make_float4(xv.x, xv.x, xv.y, xv.y);
        row[c0 * 2 + 1] = make_float4(xv.z, xv.z, xv.w, xv.w);
    }
    __syncthreads();

    int tx = t & 15, ty = t >> 4;
    uint32_t wsa = sm32(Ws) + tx * 16;
    uint32_t xsa = sm32(XsDup) + (ty * 4) * 512;

    uint64_t a0[4], a1[4];
#pragma unroll
    for (int i = 0; i < 4; i++) { a0[i] = 0ull; a1[i] = 0ull; }

#pragma unroll 8
    for (int k = 0; k < 64; k++) {
        uint64_t w01, w23;
        asm("ld.shared.v2.u64 {%0, %1}, [%2];"
            : "=l"(w01), "=l"(w23) : "r"(wsa + k * 256));
#pragma unroll
        for (int i = 0; i < 4; i++) {
            uint64_t xd;
            asm("ld.shared.u64 %0, [%1];" : "=l"(xd) : "r"(xsa + i * 512 + k * 8));
            asm("fma.rn.f32x2 %0, %1, %2, %0;" : "+l"(a0[i]) : "l"(xd), "l"(w01));
            asm("fma.rn.f32x2 %0, %1, %2, %0;" : "+l"(a1[i]) : "l"(xd), "l"(w23));
        }
    }

    // bn partial-sum scratch aliases Ws (mainloop done reading it)
    float* s_sum = Ws;
    float* s_sq = Ws + 64;
    if (mode == 3) {
        __syncthreads();
        if (t < 64) { s_sum[t] = 0.f; s_sq[t] = 0.f; }
        __syncthreads();
    }

    float4 b = bias ? ((const float4*)bias)[tx] : make_float4(0.f, 0.f, 0.f, 0.f);
    float4* Y4 = (float4*)Y;
    float4* Y24 = (float4*)Y2;
    const float4* R4 = (const float4*)res;
    float lsum[4] = {0.f, 0.f, 0.f, 0.f}, lsq[4] = {0.f, 0.f, 0.f, 0.f};
#pragma unroll
    for (int i = 0; i < 4; i++) {
        int r = row0 + ty * 4 + i;
        if (r >= M) break;
        float4 y;
        asm("mov.b64 {%0, %1}, %2;" : "=f"(y.x), "=f"(y.y) : "l"(a0[i]));
        asm("mov.b64 {%0, %1}, %2;" : "=f"(y.z), "=f"(y.w) : "l"(a1[i]));
        y.x += b.x; y.y += b.y; y.z += b.z; y.w += b.w;
        if (mode == 2) {
            y.x = mishf(y.x); y.y = mishf(y.y);
            y.z = mishf(y.z); y.w = mishf(y.w);
        }
        if (mode == 3) {
            float4 rr = R4[r * 16 + tx];
            y.x += rr.x; y.y += rr.y; y.z += rr.z; y.w += rr.w;
            lsum[0] += y.x; lsum[1] += y.y; lsum[2] += y.z; lsum[3] += y.w;
            lsq[0] += y.x * y.x; lsq[1] += y.y * y.y;
            lsq[2] += y.z * y.z; lsq[3] += y.w * y.w;
        }
        Y4[r * 16 + tx] = y;
        if (Y2) Y24[r * 16 + tx] = y;
    }
    if (mode == 3) {
        int c0 = tx * 4;
#pragma unroll
        for (int j = 0; j < 4; j++) {
            atomicAdd(&s_sum[c0 + j], lsum[j]);
            atomicAdd(&s_sq[c0 + j], lsq[j]);
        }
        __syncthreads();
        if (t < 64) {
            atomicAdd(&g_bnsum[layer * DD + t], s_sum[t]);
            atomicAdd(&g_bnsq[layer * DD + t], s_sq[t]);
        }
    }
}

// ---------------- aggregation in p-space, fused mish + replica mean ----------------
// One warp per node; lane handles 2 features. 4-wide software pipeline for MLP.
#define AGG_ACC(m, v) { \
    if ((m) & 1u) { a0.x += (v).x; a0.y += (v).y; } \
    if ((m) & 2u) { a1.x += (v).x; a1.y += (v).y; } \
    if ((m) & 4u) { a2.x += (v).x; a2.y += (v).y; } \
    if ((m) & 8u) { a3.x += (v).x; a3.y += (v).y; } }

__global__ __launch_bounds__(256) void agg_kernel(
    const float2* __restrict__ p2, const unsigned char* __restrict__ keepb,
    const float* __restrict__ b1, float2* __restrict__ tbar) {
    int gt = blockIdx.x * blockDim.x + threadIdx.x;
    int n = gt >> 5;
    int lane = gt & 31;
    if (n >= NN) return;
    unsigned mb = keepb[n];
    float2 vs = p2[n * 32 + lane];
    float2 a0, a1, a2, a3;
    a0.x = (mb & 1u) ? vs.x : 0.f; a0.y = (mb & 1u) ? vs.y : 0.f;
    a1.x = (mb & 2u) ? vs.x : 0.f; a1.y = (mb & 2u) ? vs.y : 0.f;
    a2.x = (mb & 4u) ? vs.x : 0.f; a2.y = (mb & 4u) ? vs.y : 0.f;
    a3.x = (mb & 8u) ? vs.x : 0.f; a3.y = (mb & 8u) ? vs.y : 0.f;
    int j = g_rowptr[n], end = g_rowptr[n + 1];
    for (; j + 3 < end; j += 4) {
        int s0 = g_col[j], s1 = g_col[j + 1], s2 = g_col[j + 2], s3 = g_col[j + 3];
        unsigned m0 = keepb[s0], m1 = keepb[s1], m2 = keepb[s2], m3 = keepb[s3];
        float2 v0 = p2[s0 * 32 + lane];
        float2 v1 = p2[s1 * 32 + lane];
        float2 v2 = p2[s2 * 32 + lane];
        float2 v3 = p2[s3 * 32 + lane];
        AGG_ACC(m0, v0) AGG_ACC(m1, v1) AGG_ACC(m2, v2) AGG_ACC(m3, v3)
    }
    for (; j < end; j++) {
        int s = g_col[j];
        unsigned m = keepb[s];
        float2 v = p2[s * 32 + lane];
        AGG_ACC(m, v)
    }
    float bx = b1[2 * lane], by = b1[2 * lane + 1];
    float sx = mishf(a0.x + bx) + mishf(a1.x + bx) + mishf(a2.x + bx) + mishf(a3.x + bx);
    float sy = mishf(a0.y + by) + mishf(a1.y + by) + mishf(a2.y + by) + mishf(a3.y + by);
    float2 o;
    o.x = 0.25f * sx;
    o.y = 0.25f * sy;
    tbar[n * 32 + lane] = o;
}

// ---------------- batchnorm apply (stats computed inline per block) ----------------
__global__ __launch_bounds__(256) void bn_apply(float* __restrict__ dst, int last, int layer) {
    __shared__ float st[128];  // [0..63]=mu, [64..127]=rstd
    int t = threadIdx.x;
    if (t < 64) {
        float mu = g_bnsum[layer * DD + t] * (1.f / NN);
        float var = g_bnsq[layer * DD + t] * (1.f / NN) - mu * mu;
        st[t] = mu;
        st[64 + t] = rsqrtf(var + 1e-5f);
    }
    __syncthreads();
    int base = blockIdx.x * 1024;  // float4 units (64 rows x 16)
    const float4* H4 = (const float4*)g_hnew;
    const float4* X4 = (const float4*)g_xproj;
    float4* D4 = (float4*)dst;
#pragma unroll
    for (int q = 0; q < 4; q++) {
        int idx = base + t + 256 * q;
        int r = idx >> 4;
        if (r >= NN) break;
        int c0 = (idx & 15) * 4;
        float4 v = H4[idx];
        v.x = mishf((v.x - st[c0 + 0]) * st[64 + c0 + 0]);
        v.y = mishf((v.y - st[c0 + 1]) * st[64 + c0 + 1]);
        v.z = mishf((v.z - st[c0 + 2]) * st[64 + c0 + 2]);
        v.w = mishf((v.w - st[c0 + 3]) * st[64 + c0 + 3]);
        if (last) {
            float4 xp = X4[idx];
            v.x += xp.x; v.y += xp.y; v.z += xp.z; v.w += xp.w;
        }
        D4[idx] = v;
    }
}

// ---------------- launch ----------------
extern "C" void kernel_launch(void* const* d_in, const int* in_sizes, int n_in,
                              void* d_out, int out_size) {
    const float* x    = (const float*)d_in[0];
    const void*  ei   = d_in[1];  // int32 or int64, auto-detected on device
    const float* nW1  = (const float*)d_in[2];
    const float* nb1  = (const float*)d_in[3];
    const float* nW2  = (const float*)d_in[4];
    const float* nb2  = (const float*)d_in[5];
    const float* cW1  = (const float*)d_in[6];
    const float* cb1  = (const float*)d_in[7];
    const float* cW2  = (const float*)d_in[8];
    const float* cb2  = (const float*)d_in[9];
    float* out = (float*)d_out;

    float *h, *xproj, *p, *tbar, *hnew;
    unsigned char* keepb;
    cudaGetSymbolAddress((void**)&h, g_h);
    cudaGetSymbolAddress((void**)&xproj, g_xproj);
    cudaGetSymbolAddress((void**)&p, g_p);
    cudaGetSymbolAddress((void**)&tbar, g_tbar);
    cudaGetSymbolAddress((void**)&hnew, g_hnew);
    cudaGetSymbolAddress((void**)&keepb, g_keepb);

    const int TB = 256;
    initdetect_kernel<<<(EE + TB - 1) / TB, TB>>>((const unsigned*)ei);
    count_deg<<<(EE + TB - 1) / TB, TB>>>(ei);
    scan1<<<49, 256>>>();
    scan2<<<1, 64>>>();
    scan3<<<(NN + TB - 1) / TB, TB>>>();
    fill_csr<<<(EE + TB - 1) / TB, TB>>>(ei);
    mask_kernel<<<(LL * NN + TB - 1) / TB, TB>>>();

    int GB = (NN + 63) / 64;
    // node MLP: p <- mish(x@nW1+nb1); xproj,h <- p@nW2+nb2
    gemm64<<<GB, 256>>>(x, nW1, nb1, nullptr, p, nullptr, NN, 2, 0);
    gemm64<<<GB, 256>>>(p, nW2, nb2, nullptr, xproj, h, NN, 1, 0);

    for (int l = 0; l < LL; l++) {
        gemm64<<<GB, 256>>>(h, cW1 + l * DD * DD, nullptr, nullptr, p, nullptr, NN, 0, l);
        agg_kernel<<<(NN * 32 + TB - 1) / TB, TB>>>(
            (const float2*)p, keepb + l * NN, cb1 + l * DD, (float2*)tbar);
        gemm64<<<GB, 256>>>(tbar, cW2 + l * DD * DD, cb2 + l * DD, h, hnew, nullptr, NN, 3, l);
        bn_apply<<<GB, 256>>>((l == LL - 1) ? out : h, (l == LL - 1) ? 1 : 0, l);
    }
}